// round 15
// baseline (speedup 1.0000x reference)
#include <cuda_runtime.h>
#include <cuda_bf16.h>
#include <cooperative_groups.h>
#include <math.h>

namespace cg = cooperative_groups;

#define Bb 8
#define Nb 300
#define Rr 36
#define Cc 256
#define CONF_THR 0.3f
#define IOU_THR 0.7f
#define NW 10            // ceil(Nb/32) keep-mask words

#define CG_ 8            // channel groups per ROI
#define CPB 32           // channels per unit (Cc / CG_)
#define ROI_UNITS (CG_ * Bb * Rr)   // 2304
#define NT 256

// scratch (allocation-free): selected boxes + packed (level<<1 | valid)
__device__ float4 g_selbox[Bb * Rr];
__device__ int    g_selinfo[Bb * Rr];

struct NmsS {
    unsigned long long skey[Nb];
    float4       sb[Nb];
    float        sarea[Nb];
    unsigned int srow[Nb * NW];   // suppression bit-matrix (j>i only)
    unsigned int validw[NW];
    unsigned int keepw[NW];
};
struct RoiS {
    int4   soff[196];
    float4 swts[196];
};
union SmemU {
    NmsS n;
    RoiS r;
};

__device__ __forceinline__
void nms_part(int b, const float* __restrict__ boxes,
              const float* __restrict__ scores, NmsS& S)
{
    const int tid = threadIdx.x;

    // ---- build sort keys: descending score (thresholded), stable by index ----
    for (int i = tid; i < Nb; i += NT) {
        float s  = scores[b * Nb + i];
        float sv = (s > CONF_THR) ? s : -INFINITY;
        unsigned int bits = __float_as_uint(sv);
        unsigned int u = bits ^ ((bits >> 31) ? 0xFFFFFFFFu : 0x80000000u);
        // smaller key = higher score (lower index on tie) -> rank = sorted pos
        S.skey[i] = (((unsigned long long)(~u)) << 32) | (unsigned int)i;
    }
    if (tid < NW) S.validw[tid] = 0u;
    __syncthreads();

    // ---- rank sort: exact stable argsort(-s) ----
    for (int i = tid; i < Nb; i += NT) {
        unsigned long long mykey = S.skey[i];
        int r = 0;
        #pragma unroll 10
        for (int j = 0; j < Nb; j++) r += (S.skey[j] < mykey);
        const float* bp = boxes + ((size_t)b * Nb + i) * 4;
        float4 bx = make_float4(bp[0], bp[1], bp[2], bp[3]);
        S.sb[r]    = bx;
        S.sarea[r] = (bx.z - bx.x) * (bx.w - bx.y);
        float s = scores[b * Nb + i];
        if (s > CONF_THR) atomicOr(&S.validw[r >> 5], 1u << (r & 31));
    }
    __syncthreads();

    // ---- suppression bit matrix: bit j of word (i,w) set iff j>i & iou>THR ----
    for (int t = tid; t < Nb * NW; t += NT) {
        int i = t / NW;
        int w = t - i * NW;
        unsigned int bits = 0u;
        int j0 = w << 5;
        if (j0 + 31 > i) {
            float4 bi = S.sb[i];
            float  ai = S.sarea[i];
            int jbeg = max(j0, i + 1);
            int jend = min(j0 + 32, Nb);
            for (int j = jbeg; j < jend; j++) {
                float4 bj = S.sb[j];
                float ltx = fmaxf(bi.x, bj.x);
                float lty = fmaxf(bi.y, bj.y);
                float rbx = fminf(bi.z, bj.z);
                float rby = fminf(bi.w, bj.w);
                float ww = fmaxf(rbx - ltx, 0.0f);
                float hh = fmaxf(rby - lty, 0.0f);
                float inter = ww * hh;
                float iou = inter / (ai + S.sarea[j] - inter + 1e-9f);
                if (iou > IOU_THR) bits |= 1u << (j - j0);
            }
        }
        S.srow[t] = bits;
    }
    __syncthreads();

    // ---- greedy suppression: single warp, no barriers ----
    if (tid < 32) {
        unsigned int kw   = (tid < NW) ? S.validw[tid] : 0u;
        unsigned int nrow = (tid < NW) ? S.srow[tid]   : 0u;
        for (int i = 0; i < Nb; i++) {
            unsigned int row = nrow;
            if (tid < NW && i + 1 < Nb) nrow = S.srow[(i + 1) * NW + tid];
            unsigned int wi = __shfl_sync(0xFFFFFFFFu, kw, i >> 5);
            if ((wi >> (i & 31)) & 1u) kw &= ~row;
        }
        if (tid < NW) S.keepw[tid] = kw;
    }
    __syncthreads();

    // ---- parallel stable partition (kept first), take first Rr, FPN level ----
    for (int i = tid; i < Nb; i += NT) {
        int w   = i >> 5;
        int bit = i & 31;
        unsigned int myw = S.keepw[w];
        int kept = (myw >> bit) & 1;
        int kpre = __popc(myw & ((1u << bit) - 1u));
        for (int u = 0; u < w; u++) kpre += __popc(S.keepw[u]);
        int K = 0;
        #pragma unroll
        for (int u = 0; u < NW; u++) K += __popc(S.keepw[u]);
        int slot = kept ? kpre : (K + (i - kpre));
        if (slot < Rr) {
            float4 bx = S.sb[i];
            g_selbox[b * Rr + slot] = bx;
            float dx = bx.z - bx.x;
            float dy = bx.w - bx.y;
            float size = sqrtf(fmaxf(dx * dx + dy * dy, 1e-12f));
            float t = floorf(4.0f + log2f(size / 224.0f * 4.0f));
            t = fminf(fmaxf(t, 2.0f), 5.0f);
            int lv = (int)t - 2;
            g_selinfo[b * Rr + slot] = (lv << 1) | kept;
        }
    }
    __threadfence();   // publish before grid sync (8 blocks only; cheap)
}

__device__ __forceinline__
void roi_unit(int wu, const float* __restrict__ f0, const float* __restrict__ f1,
              const float* __restrict__ f2, const float* __restrict__ f3,
              float* __restrict__ out, RoiS& S)
{
    const int cg  = wu & (CG_ - 1);
    const int rid = wu >> 3;             // / CG_
    const int b   = rid / Rr;
    const int tid = threadIdx.x;
    float* o = out + (size_t)rid * Cc + cg * CPB;

    const int info = g_selinfo[rid];
    if (!(info & 1)) {                   // invalid ROI -> zeros
        if (tid < CPB) o[tid] = 0.0f;
        return;
    }

    const int lv = info >> 1;
    const float* feat;
    int H, W;
    if      (lv == 0) { feat = f0; H = 200; W = 200; }
    else if (lv == 1) { feat = f1; H = 100; W = 100; }
    else if (lv == 2) { feat = f2; H = 50;  W = 50;  }
    else              { feat = f3; H = 25;  W = 25;  }
    const int HW = H * W;
    const float* fb = feat + ((size_t)b * Cc + cg * CPB) * HW;

    const float4 bx = g_selbox[rid];
    const float rw = fmaxf(bx.z - bx.x, 1.0f);
    const float rh = fmaxf(bx.w - bx.y, 1.0f);

    if (tid < 196) {
        int gy = tid / 14;
        int gx = tid - gy * 14;
        float Y = bx.y + rh * ((gy + 0.5f) / 14.0f);
        float X = bx.x + rw * ((gx + 0.5f) / 14.0f);
        float Hf = (float)H, Wf = (float)W;
        bool oob = (Y < -1.0f) || (Y > Hf) || (X < -1.0f) || (X > Wf);
        float y = fminf(fmaxf(Y, 0.0f), Hf - 1.0f);
        float x = fminf(fmaxf(X, 0.0f), Wf - 1.0f);
        int y0 = (int)floorf(y);
        int x0 = (int)floorf(x);
        int y1i = min(y0 + 1, H - 1);
        int x1i = min(x0 + 1, W - 1);
        float ly = y - (float)y0;
        float lx = x - (float)x0;
        float w00 = (1.0f - ly) * (1.0f - lx);
        float w01 = (1.0f - ly) * lx;
        float w10 = ly * (1.0f - lx);
        float w11 = ly * lx;
        if (oob) {
            w00 = w01 = w10 = w11 = 0.0f;
            S.soff[tid] = make_int4(0, 0, 0, 0);
        } else {
            S.soff[tid] = make_int4(y0 * W + x0, y0 * W + x1i, y1i * W + x0, y1i * W + x1i);
        }
        S.swts[tid] = make_float4(w00, w01, w10, w11);
    }
    __syncthreads();

    const int warp = tid >> 5;
    const int lane = tid & 31;
    const int c0 = warp * 4;
    const float* fB = fb + (size_t)c0 * HW;

    float acc[4] = {0.0f, 0.0f, 0.0f, 0.0f};

    #pragma unroll
    for (int k = 0; k < 7; k++) {
        int p  = lane + 32 * k;
        int sp = (p < 196) ? p : 0;
        int4   oo = S.soff[sp];
        float4 ww = S.swts[sp];
        if (p >= 196) ww = make_float4(0.0f, 0.0f, 0.0f, 0.0f);
        float v[4][4];
        #pragma unroll
        for (int c = 0; c < 4; c++) {
            const float* f = fB + c * HW;
            v[c][0] = f[oo.x];
            v[c][1] = f[oo.y];
            v[c][2] = f[oo.z];
            v[c][3] = f[oo.w];
        }
        #pragma unroll
        for (int c = 0; c < 4; c++) {
            acc[c] += v[c][0] * ww.x + v[c][1] * ww.y + v[c][2] * ww.z + v[c][3] * ww.w;
        }
    }

    #pragma unroll
    for (int s = 16; s; s >>= 1) {
        acc[0] += __shfl_down_sync(0xFFFFFFFFu, acc[0], s);
        acc[1] += __shfl_down_sync(0xFFFFFFFFu, acc[1], s);
        acc[2] += __shfl_down_sync(0xFFFFFFFFu, acc[2], s);
        acc[3] += __shfl_down_sync(0xFFFFFFFFu, acc[3], s);
    }
    if (lane == 0) {
        o[c0 + 0] = acc[0] * (1.0f / 196.0f);
        o[c0 + 1] = acc[1] * (1.0f / 196.0f);
        o[c0 + 2] = acc[2] * (1.0f / 196.0f);
        o[c0 + 3] = acc[3] * (1.0f / 196.0f);
    }
}

__global__ void __launch_bounds__(NT, 6)
fused_coop_kernel(const float* __restrict__ boxes, const float* __restrict__ scores,
                  const float* __restrict__ f0, const float* __restrict__ f1,
                  const float* __restrict__ f2, const float* __restrict__ f3,
                  float* __restrict__ out)
{
    __shared__ SmemU S;
    const int bid  = blockIdx.x;
    const int gsz  = gridDim.x;

    // Phase 1: blocks 0..7 run NMS (one batch each); others go straight to sync.
    if (bid < Bb) {
        nms_part(bid, boxes, scores, S.n);
    }

    cg::this_grid().sync();   // execution + memory barrier across the grid

    // Phase 2: grid-stride over all 2304 roi units.
    for (int wu = bid; wu < ROI_UNITS; wu += gsz) {
        __syncthreads();      // protect smem union reuse between iterations/phases
        roi_unit(wu, f0, f1, f2, f3, out, S.r);
    }
}

extern "C" void kernel_launch(void* const* d_in, const int* in_sizes, int n_in,
                              void* d_out, int out_size)
{
    const float* boxes  = (const float*)d_in[0]; // (B,N,4)
    const float* scores = (const float*)d_in[1]; // (B,N)
    const float* f0     = (const float*)d_in[2]; // (B,C,200,200)
    const float* f1     = (const float*)d_in[3]; // (B,C,100,100)
    const float* f2     = (const float*)d_in[4]; // (B,C,50,50)
    const float* f3     = (const float*)d_in[5]; // (B,C,25,25)
    float* out          = (float*)d_out;         // (B,R,C)

    // Size the cooperative grid to guaranteed co-residency (host-side queries,
    // no stream ops -> capture-safe, deterministic).
    int dev = 0;
    cudaGetDevice(&dev);
    int sms = 0;
    cudaDeviceGetAttribute(&sms, cudaDevAttrMultiProcessorCount, dev);
    int perSM = 0;
    cudaOccupancyMaxActiveBlocksPerMultiprocessor(&perSM, fused_coop_kernel, NT, 0);
    int grid = sms * perSM;
    if (grid > ROI_UNITS) grid = ROI_UNITS;   // never need more blocks than units
    if (grid < Bb) grid = Bb;                 // need at least the 8 NMS blocks

    void* args[] = { (void*)&boxes, (void*)&scores, (void*)&f0, (void*)&f1,
                     (void*)&f2, (void*)&f3, (void*)&out };
    cudaLaunchCooperativeKernel((void*)fused_coop_kernel,
                                dim3(grid), dim3(NT), args, 0, (cudaStream_t)0);
}

// round 16
// speedup vs baseline: 1.6702x; 1.6702x over previous
#include <cuda_runtime.h>
#include <cuda_bf16.h>
#include <math.h>

#define Bb 8
#define Nb 300
#define Rr 36
#define Cc 256
#define NMS_T 512
#define CONF_THR 0.3f
#define IOU_THR 0.7f
#define NW 10          // ceil(Nb/32) keep-mask words

#define CG 8           // channel groups per ROI
#define CPB 32         // channels per block (Cc / CG)
#define ROI_BLOCKS (CG * Bb * Rr)   // 2304

// scratch (allocation-free): selected boxes + packed (level<<1 | valid)
__device__ float4 g_selbox[Bb * Rr];
__device__ int    g_selinfo[Bb * Rr];

// Launched with a FULL-CHIP grid; only blocks 0..7 do real work, the rest
// exit immediately. This probes/neutralizes the tiny-grid first-node cost.
__global__ __launch_bounds__(NMS_T)
void nms_kernel(const float* __restrict__ boxes, const float* __restrict__ scores)
{
    const int b   = blockIdx.x;
    const int tid = threadIdx.x;
    if (b >= Bb) return;     // filler blocks: exit immediately

    __shared__ unsigned long long skey[Nb];
    __shared__ float4       sb[Nb];
    __shared__ float        sarea[Nb];
    __shared__ unsigned int srow[Nb * NW];   // suppression bit-matrix (j>i only)
    __shared__ unsigned int validw[NW];
    __shared__ unsigned int keepw[NW];

    // ---- build sort keys: descending score (thresholded), stable by index ----
    float myscore = 0.0f;
    if (tid < Nb) {
        float s  = scores[b * Nb + tid];
        myscore  = s;
        float sv = (s > CONF_THR) ? s : -INFINITY;
        unsigned int bits = __float_as_uint(sv);
        unsigned int u = bits ^ ((bits >> 31) ? 0xFFFFFFFFu : 0x80000000u);
        // smaller key = higher score (lower index on tie) -> rank = sorted pos
        skey[tid] = (((unsigned long long)(~u)) << 32) | (unsigned int)tid;
    }
    if (tid < NW) validw[tid] = 0u;
    __syncthreads();

    // ---- rank sort: exact stable argsort(-s), zero extra barriers ----
    if (tid < Nb) {
        unsigned long long mykey = skey[tid];
        int r = 0;
        #pragma unroll 10
        for (int j = 0; j < Nb; j++) r += (skey[j] < mykey);
        const float* bp = boxes + ((size_t)b * Nb + tid) * 4;
        float4 bx = make_float4(bp[0], bp[1], bp[2], bp[3]);
        sb[r]    = bx;
        sarea[r] = (bx.z - bx.x) * (bx.w - bx.y);
        if (myscore > CONF_THR) atomicOr(&validw[r >> 5], 1u << (r & 31));
    }
    __syncthreads();

    // ---- suppression bit matrix: bit j of word (i,w) set iff j>i & iou>THR ----
    for (int t = tid; t < Nb * NW; t += NMS_T) {
        int i = t / NW;
        int w = t - i * NW;
        unsigned int bits = 0u;
        int j0 = w << 5;
        if (j0 + 31 > i) {
            float4 bi = sb[i];
            float  ai = sarea[i];
            int jbeg = max(j0, i + 1);
            int jend = min(j0 + 32, Nb);
            for (int j = jbeg; j < jend; j++) {
                float4 bj = sb[j];
                float ltx = fmaxf(bi.x, bj.x);
                float lty = fmaxf(bi.y, bj.y);
                float rbx = fminf(bi.z, bj.z);
                float rby = fminf(bi.w, bj.w);
                float ww = fmaxf(rbx - ltx, 0.0f);
                float hh = fmaxf(rby - lty, 0.0f);
                float inter = ww * hh;
                float iou = inter / (ai + sarea[j] - inter + 1e-9f);
                if (iou > IOU_THR) bits |= 1u << (j - j0);
            }
        }
        srow[t] = bits;
    }
    __syncthreads();

    // ---- greedy suppression: single warp, no barriers ----
    if (tid < 32) {
        unsigned int kw   = (tid < NW) ? validw[tid] : 0u;
        unsigned int nrow = (tid < NW) ? srow[tid]   : 0u;
        for (int i = 0; i < Nb; i++) {
            unsigned int row = nrow;
            if (tid < NW && i + 1 < Nb) nrow = srow[(i + 1) * NW + tid];
            unsigned int wi = __shfl_sync(0xFFFFFFFFu, kw, i >> 5);
            if ((wi >> (i & 31)) & 1u) kw &= ~row;
        }
        if (tid < NW) keepw[tid] = kw;
    }
    __syncthreads();

    // ---- parallel stable partition (kept first), take first Rr, FPN level ----
    if (tid < Nb) {
        int w   = tid >> 5;
        int bit = tid & 31;
        unsigned int myw = keepw[w];
        int kept = (myw >> bit) & 1;
        int kpre = __popc(myw & ((1u << bit) - 1u));
        for (int u = 0; u < w; u++) kpre += __popc(keepw[u]);
        int K = 0;
        #pragma unroll
        for (int u = 0; u < NW; u++) K += __popc(keepw[u]);
        int slot = kept ? kpre : (K + (tid - kpre));
        if (slot < Rr) {
            float4 bx = sb[tid];
            g_selbox[b * Rr + slot] = bx;
            float dx = bx.z - bx.x;
            float dy = bx.w - bx.y;
            float size = sqrtf(fmaxf(dx * dx + dy * dy, 1e-12f));
            float t = floorf(4.0f + log2f(size / 224.0f * 4.0f));
            t = fminf(fmaxf(t, 2.0f), 5.0f);
            int lv = (int)t - 2;
            g_selinfo[b * Rr + slot] = (lv << 1) | kept;
        }
    }
}

// grid: (CG, B*R). 256 threads = 8 warps; each warp does 4 channels.
// Per k-step: 16 independent LDGs (4 corners x 4 channels); 7 k-steps unrolled.
__global__ __launch_bounds__(256)
void roi_kernel(const float* __restrict__ f0, const float* __restrict__ f1,
                const float* __restrict__ f2, const float* __restrict__ f3,
                float* __restrict__ out)
{
    const int cg  = blockIdx.x;          // 0 .. CG-1
    const int rid = blockIdx.y;          // 0 .. B*R-1
    const int b   = rid / Rr;
    const int tid = threadIdx.x;
    float* o = out + (size_t)rid * Cc + cg * CPB;

    const int info = g_selinfo[rid];
    if (!(info & 1)) {                   // invalid ROI -> zeros
        if (tid < CPB) o[tid] = 0.0f;
        return;
    }

    const int lv = info >> 1;
    const float* feat;
    int H, W;
    if      (lv == 0) { feat = f0; H = 200; W = 200; }
    else if (lv == 1) { feat = f1; H = 100; W = 100; }
    else if (lv == 2) { feat = f2; H = 50;  W = 50;  }
    else              { feat = f3; H = 25;  W = 25;  }
    const int HW = H * W;
    const float* fb = feat + ((size_t)b * Cc + cg * CPB) * HW;

    const float4 bx = g_selbox[rid];
    const float rw = fmaxf(bx.z - bx.x, 1.0f);
    const float rh = fmaxf(bx.w - bx.y, 1.0f);

    __shared__ int4   soff[196];
    __shared__ float4 swts[196];

    if (tid < 196) {
        int gy = tid / 14;
        int gx = tid - gy * 14;
        float Y = bx.y + rh * ((gy + 0.5f) / 14.0f);
        float X = bx.x + rw * ((gx + 0.5f) / 14.0f);
        float Hf = (float)H, Wf = (float)W;
        bool oob = (Y < -1.0f) || (Y > Hf) || (X < -1.0f) || (X > Wf);
        float y = fminf(fmaxf(Y, 0.0f), Hf - 1.0f);
        float x = fminf(fmaxf(X, 0.0f), Wf - 1.0f);
        int y0 = (int)floorf(y);
        int x0 = (int)floorf(x);
        int y1i = min(y0 + 1, H - 1);
        int x1i = min(x0 + 1, W - 1);
        float ly = y - (float)y0;
        float lx = x - (float)x0;
        float w00 = (1.0f - ly) * (1.0f - lx);
        float w01 = (1.0f - ly) * lx;
        float w10 = ly * (1.0f - lx);
        float w11 = ly * lx;
        if (oob) {
            w00 = w01 = w10 = w11 = 0.0f;
            soff[tid] = make_int4(0, 0, 0, 0);
        } else {
            soff[tid] = make_int4(y0 * W + x0, y0 * W + x1i, y1i * W + x0, y1i * W + x1i);
        }
        swts[tid] = make_float4(w00, w01, w10, w11);
    }
    __syncthreads();

    const int warp = tid >> 5;
    const int lane = tid & 31;

    const int c0 = warp * 4;
    const float* fB = fb + (size_t)c0 * HW;

    float acc[4] = {0.0f, 0.0f, 0.0f, 0.0f};

    #pragma unroll
    for (int k = 0; k < 7; k++) {
        int p  = lane + 32 * k;
        int sp = (p < 196) ? p : 0;
        int4   oo = soff[sp];
        float4 ww = swts[sp];
        if (p >= 196) ww = make_float4(0.0f, 0.0f, 0.0f, 0.0f);
        // 16 independent loads before any FMA
        float v[4][4];
        #pragma unroll
        for (int c = 0; c < 4; c++) {
            const float* f = fB + c * HW;
            v[c][0] = f[oo.x];
            v[c][1] = f[oo.y];
            v[c][2] = f[oo.z];
            v[c][3] = f[oo.w];
        }
        #pragma unroll
        for (int c = 0; c < 4; c++) {
            acc[c] += v[c][0] * ww.x + v[c][1] * ww.y + v[c][2] * ww.z + v[c][3] * ww.w;
        }
    }

    #pragma unroll
    for (int s = 16; s; s >>= 1) {
        acc[0] += __shfl_down_sync(0xFFFFFFFFu, acc[0], s);
        acc[1] += __shfl_down_sync(0xFFFFFFFFu, acc[1], s);
        acc[2] += __shfl_down_sync(0xFFFFFFFFu, acc[2], s);
        acc[3] += __shfl_down_sync(0xFFFFFFFFu, acc[3], s);
    }
    if (lane == 0) {
        o[c0 + 0] = acc[0] * (1.0f / 196.0f);
        o[c0 + 1] = acc[1] * (1.0f / 196.0f);
        o[c0 + 2] = acc[2] * (1.0f / 196.0f);
        o[c0 + 3] = acc[3] * (1.0f / 196.0f);
    }
}

extern "C" void kernel_launch(void* const* d_in, const int* in_sizes, int n_in,
                              void* d_out, int out_size)
{
    const float* boxes  = (const float*)d_in[0]; // (B,N,4)
    const float* scores = (const float*)d_in[1]; // (B,N)
    const float* f0     = (const float*)d_in[2]; // (B,C,200,200)
    const float* f1     = (const float*)d_in[3]; // (B,C,100,100)
    const float* f2     = (const float*)d_in[4]; // (B,C,50,50)
    const float* f3     = (const float*)d_in[5]; // (B,C,25,25)
    float* out          = (float*)d_out;         // (B,R,C)

    // Full-chip grid for the first node: blocks 8..2311 exit immediately.
    nms_kernel<<<Bb + ROI_BLOCKS, NMS_T>>>(boxes, scores);
    dim3 grid(CG, Bb * Rr);
    roi_kernel<<<grid, 256>>>(f0, f1, f2, f3, out);
}